// round 5
// baseline (speedup 1.0000x reference)
#include <cuda_runtime.h>
#include <math.h>
#include <stdint.h>

#define BB 4096
#define EE 128
#define MMOD 8
#define NSTEPS 3
#define HDIM 256
#define CDIM 16
#define RT 16                  // rows per tile
#define NPAIR (RT/2)           // 8 row-pairs
#define NTHR 256
#define MAX_TILES (BB/RT + MMOD)   // 264

#define CHUNK_F 4096           // floats per weight chunk buffer (16KB)
#define DYN_SMEM ((4096 + 3*CHUNK_F) * 4)   // 16KB tile + 3x16KB bufs = 64KB

typedef unsigned long long ull;

// Scratch (static __device__ — no allocation allowed)
__device__ float g_X[BB * EE];                    // recurrent state, 2 MB
__device__ int   g_order[NSTEPS * BB];            // per-step rows sorted by module
__device__ int   g_tiles[NSTEPS * MAX_TILES * 3]; // (module, base, cnt) per tile

// ---------------- f32x2 helpers (FFMA2 path, sm_103a) ----------------------
__device__ __forceinline__ ull bcast2(float v) {
    ull r; asm("mov.b64 %0, {%1, %1};" : "=l"(r) : "f"(v)); return r;
}
__device__ __forceinline__ ull fma2(ull a, ull b, ull c) {
    ull d; asm("fma.rn.f32x2 %0, %1, %2, %3;" : "=l"(d) : "l"(a), "l"(b), "l"(c));
    return d;
}
__device__ __forceinline__ float2 unpack2(ull v) {
    float2 f; asm("mov.b64 {%0, %1}, %2;" : "=f"(f.x), "=f"(f.y) : "l"(v)); return f;
}
// ---------------- cp.async helpers ----------------------------------------
__device__ __forceinline__ uint32_t sptr(const void* p) {
    return (uint32_t)__cvta_generic_to_shared(p);
}
__device__ __forceinline__ void cpa16(uint32_t s, const float* g) {
    asm volatile("cp.async.ca.shared.global [%0], [%1], 16;" :: "r"(s), "l"(g));
}
__device__ __forceinline__ void cpa_commit() {
    asm volatile("cp.async.commit_group;");
}
__device__ __forceinline__ void cpa_wait1() {
    asm volatile("cp.async.wait_group 1;");
}
__device__ __forceinline__ void cpa_wait0() {
    asm volatile("cp.async.wait_group 0;");
}

// ---------------------------------------------------------------------------
// Setup: per-step counting sort of rows by module + tile metadata
// ---------------------------------------------------------------------------
__global__ void setup_kernel(const int* __restrict__ module_ids) {
    __shared__ int cnt[MMOD], cur[MMOD];
    int tid = threadIdx.x;
    for (int s = 0; s < NSTEPS; s++) {
        if (tid < MMOD) cnt[tid] = 0;
        __syncthreads();
        for (int b = tid; b < BB; b += NTHR)
            atomicAdd(&cnt[module_ids[b * NSTEPS + s]], 1);
        __syncthreads();
        if (tid == 0) {
            int o = 0, t = 0;
            for (int m = 0; m < MMOD; m++) {
                cur[m] = o;
                int c = cnt[m];
                for (int chunk = 0; chunk < c; chunk += RT) {
                    g_tiles[(s * MAX_TILES + t) * 3 + 0] = m;
                    g_tiles[(s * MAX_TILES + t) * 3 + 1] = o + chunk;
                    g_tiles[(s * MAX_TILES + t) * 3 + 2] = min(RT, c - chunk);
                    t++;
                }
                o += c;
            }
            for (; t < MAX_TILES; t++)
                g_tiles[(s * MAX_TILES + t) * 3 + 2] = 0;
        }
        __syncthreads();
        for (int b = tid; b < BB; b += NTHR) {
            int m = module_ids[b * NSTEPS + s];
            int p = atomicAdd(&cur[m], 1);
            g_order[s * BB + p] = b;
        }
        __syncthreads();
    }
}

// ---------------------------------------------------------------------------
// One recurrent step for one (module, 16-row tile). Row-PAIR packed f32x2.
// Triple-buffered cp.async weight pipeline, 1 sync per chunk.
// Dynamic SMEM floats: [0,4096) tile (X|B then H as float2), then 3x4096 bufs.
// 256 threads: o = tid&127 (output col), g = tid>>7 (0..1) -> pairs 4g..4g+3.
// Unified chunk ids: 0..7 = phase1 (Wi+Wb, 16 e-rows), 8..15 = phase2 (Wf, 32 f-rows).
// ---------------------------------------------------------------------------
__device__ __forceinline__ void step_prefetch(int gc, int buf, int tid,
                                              float* arena,
                                              const float* Wi, const float* Wb,
                                              const float* Wf) {
    uint32_t d = sptr(arena + buf * CHUNK_F);
    if (gc < 8) {
        const float* si = Wi + gc * 2048;
        const float* sb = Wb + gc * 2048;
        cpa16(d + tid * 16,        si + tid * 4);
        cpa16(d + tid * 16 + 4096, si + tid * 4 + 1024);
        cpa16(d + tid * 16 + 8192, sb + tid * 4);
        cpa16(d + tid * 16 + 12288, sb + tid * 4 + 1024);
    } else {
        const float* sf = Wf + (gc - 8) * 4096;
        cpa16(d + tid * 16,         sf + tid * 4);
        cpa16(d + tid * 16 + 4096,  sf + tid * 4 + 1024);
        cpa16(d + tid * 16 + 8192,  sf + tid * 4 + 2048);
        cpa16(d + tid * 16 + 12288, sf + tid * 4 + 3072);
    }
    cpa_commit();
}

__global__ __launch_bounds__(NTHR, 2)
void step_kernel(int s,
                 const float* __restrict__ emb,
                 const int* __restrict__ entity_ids,
                 const float* __restrict__ W_in,  const float* __restrict__ b_in,
                 const float* __restrict__ W_bias,const float* __restrict__ b_bias,
                 const float* __restrict__ W_f,   const float* __restrict__ b_f) {
    extern __shared__ float dynsm[];
    float2* SH    = (float2*)dynsm;        // 2048 float2 tile region
    float*  SHf   = dynsm;
    float*  ARENA = dynsm + 4096;          // 3 weight buffers
    __shared__ int ridx[RT], xrow[RT], eidn[RT];
    __shared__ int s_m, s_cnt;

    int tid = threadIdx.x;
    if (tid == 0) {
        int t = blockIdx.x;
        s_m   = g_tiles[(s * MAX_TILES + t) * 3 + 0];
        s_cnt = g_tiles[(s * MAX_TILES + t) * 3 + 2];
    }
    if (tid < RT) {
        int t = blockIdx.x;
        int base = g_tiles[(s * MAX_TILES + t) * 3 + 1];
        int cnt0 = g_tiles[(s * MAX_TILES + t) * 3 + 2];
        int row = (cnt0 > 0) ? g_order[s * BB + base + ((tid < cnt0) ? tid : 0)] : 0;
        ridx[tid] = row;
        xrow[tid] = (s == 0) ? entity_ids[row * (NSTEPS + 1)] : row;
        eidn[tid] = entity_ids[row * (NSTEPS + 1) + s + 1];
    }
    __syncthreads();
    const int cnt = s_cnt;
    if (cnt == 0) return;
    const int m = s_m;

    const float* Wi = W_in   + m * EE * EE;
    const float* Wb = W_bias + m * EE * EE;
    const float* Wf = W_f    + m * 2 * EE * EE;
    const float* Xsrc = (s == 0) ? emb : g_X;

    // Prime pipeline: chunks 0,1
    step_prefetch(0, 0, tid, ARENA, Wi, Wb, Wf);
    step_prefetch(1, 1, tid, ARENA, Wi, Wb, Wf);

    // Gather X tile + Bias tile into pair-interleaved SMEM
    // X: float idx p*256 + 2e + comp  (p=pair, comp=row&1), region [0,2048)
    // B: float idx 2048 + p*256 + 2e + comp, region [2048,4096)
    for (int i = tid; i < RT * EE; i += NTHR) {
        int r = i >> 7, e = i & (EE - 1);
        int p = r >> 1, comp = r & 1;
        SHf[p * 256 + 2 * e + comp]        = Xsrc[(size_t)xrow[r] * EE + e];
        SHf[2048 + p * 256 + 2 * e + comp] = emb[(size_t)eidn[r] * EE + e];
    }

    const int o  = tid & (EE - 1);
    const int g  = tid >> 7;     // 0..1
    const int p0 = g * 4;

    ull accI[4], accB[4];
#pragma unroll
    for (int p = 0; p < 4; p++) { accI[p] = 0ull; accB[p] = 0ull; }

    // ---------------- Phase 1: chunks 0..7 (16 e-rows each) ----------------
#pragma unroll
    for (int gc = 0; gc < 8; gc++) {
        cpa_wait1();             // chunk gc arrived (gc+1 may be in flight)
        __syncthreads();         // data visible + prev chunk compute done
        step_prefetch(gc + 2, (gc + 2) % 3, tid, ARENA, Wi, Wb, Wf);
        const float* WB = ARENA + (gc % 3) * CHUNK_F;
        const int e0 = gc * 16;
#pragma unroll
        for (int e = 0; e < 16; e += 2) {
            ull wi0 = bcast2(WB[(e + 0) * EE + o]);
            ull wi1 = bcast2(WB[(e + 1) * EE + o]);
            ull wb0 = bcast2(WB[2048 + (e + 0) * EE + o]);
            ull wb1 = bcast2(WB[2048 + (e + 1) * EE + o]);
            int ge = e0 + e;
#pragma unroll
            for (int p = 0; p < 4; p++) {
                int pp = p0 + p;
                ulonglong2 x2 = *(const ulonglong2*)&SH[pp * 128 + ge];
                accI[p] = fma2(x2.x, wi0, accI[p]);
                accI[p] = fma2(x2.y, wi1, accI[p]);
                ulonglong2 b2 = *(const ulonglong2*)&SH[1024 + pp * 128 + ge];
                accB[p] = fma2(b2.x, wb0, accB[p]);
                accB[p] = fma2(b2.y, wb1, accB[p]);
            }
        }
    }

    // H writeback (overwrites X|B region): H(p,f) = SH[p*256+f] as float2
    const float bi = b_in[m * EE + o];
    const float bb = b_bias[m * EE + o];
    __syncthreads();             // everyone done reading X/B
#pragma unroll
    for (int p = 0; p < 4; p++) {
        int pp = p0 + p;
        float2 vI = unpack2(accI[p]);
        float2 vB = unpack2(accB[p]);
        SH[pp * 256 + o]      = make_float2(fmaxf(vI.x + bi, 0.f), fmaxf(vI.y + bi, 0.f));
        SH[pp * 256 + EE + o] = make_float2(fmaxf(vB.x + bb, 0.f), fmaxf(vB.y + bb, 0.f));
    }

    // ---------------- Phase 2: chunks 8..15 (32 f-rows each) ---------------
    ull accF[4];
#pragma unroll
    for (int p = 0; p < 4; p++) accF[p] = 0ull;
#pragma unroll
    for (int gc = 8; gc < 16; gc++) {
        if (gc < 15) cpa_wait1(); else cpa_wait0();
        __syncthreads();         // (gc==8: also publishes H)
        if (gc + 2 < 16)
            step_prefetch(gc + 2, (gc + 2) % 3, tid, ARENA, Wi, Wb, Wf);
        const float* WB = ARENA + (gc % 3) * CHUNK_F;
        const int f0 = (gc - 8) * 32;
#pragma unroll
        for (int f = 0; f < 32; f += 2) {
            ull w0 = bcast2(WB[(f + 0) * EE + o]);
            ull w1 = bcast2(WB[(f + 1) * EE + o]);
            int gf = f0 + f;
#pragma unroll
            for (int p = 0; p < 4; p++) {
                int pp = p0 + p;
                ulonglong2 h2 = *(const ulonglong2*)&SH[pp * 256 + gf];
                accF[p] = fma2(h2.x, w0, accF[p]);
                accF[p] = fma2(h2.y, w1, accF[p]);
            }
        }
    }

    const float bf = b_f[m * EE + o];
#pragma unroll
    for (int p = 0; p < 4; p++) {
        int pp = p0 + p;
        float2 v = unpack2(accF[p]);
        int ra = 2 * pp, rb = 2 * pp + 1;
        if (ra < cnt) g_X[ridx[ra] * EE + o] = tanhf(v.x + bf);
        if (rb < cnt) g_X[ridx[rb] * EE + o] = tanhf(v.y + bf);
    }
}

// ---------------------------------------------------------------------------
// Head: out = relu(X @ W1 + b1) @ W2 + b2. 16-row tiles, 256 threads.
// Chunks 0..7 = W1 (16 e-rows x 256 = 16KB), chunk 8 = W2 (16KB).
// ---------------------------------------------------------------------------
__device__ __forceinline__ void head_prefetch(int gc, int buf, int tid,
                                              float* arena,
                                              const float* W1, const float* W2) {
    uint32_t d = sptr(arena + buf * CHUNK_F);
    const float* src = (gc < 8) ? (W1 + gc * 4096) : W2;
    cpa16(d + tid * 16,         src + tid * 4);
    cpa16(d + tid * 16 + 4096,  src + tid * 4 + 1024);
    cpa16(d + tid * 16 + 8192,  src + tid * 4 + 2048);
    cpa16(d + tid * 16 + 12288, src + tid * 4 + 3072);
    cpa_commit();
}

__global__ __launch_bounds__(NTHR, 2)
void head_kernel(const float* __restrict__ W1, const float* __restrict__ b1,
                 const float* __restrict__ W2, const float* __restrict__ b2,
                 float* __restrict__ out) {
    extern __shared__ float dynsm[];
    float2* SH    = (float2*)dynsm;        // X: (p,e)=SH[p*128+e]; H: (p,h)=SH[p*256+h]
    float*  SHf   = dynsm;
    float*  ARENA = dynsm + 4096;
    int tid  = threadIdx.x;
    int row0 = blockIdx.x * RT;

    head_prefetch(0, 0, tid, ARENA, W1, W2);
    head_prefetch(1, 1, tid, ARENA, W1, W2);

    for (int i = tid; i < RT * EE; i += NTHR) {
        int r = i >> 7, e = i & (EE - 1);
        int p = r >> 1, comp = r & 1;
        SHf[p * 256 + 2 * e + comp] = g_X[(row0 + r) * EE + e];
    }

    const int oh = tid;  // 0..255
    ull acc[8];
#pragma unroll
    for (int p = 0; p < 8; p++) acc[p] = 0ull;

#pragma unroll
    for (int gc = 0; gc < 8; gc++) {
        cpa_wait1();
        __syncthreads();
        if (gc + 2 <= 8)
            head_prefetch(gc + 2, (gc + 2) % 3, tid, ARENA, W1, W2);
        const float* WB = ARENA + (gc % 3) * CHUNK_F;
        const int e0 = gc * 16;
#pragma unroll
        for (int e = 0; e < 16; e += 2) {
            ull w0 = bcast2(WB[(e + 0) * HDIM + oh]);
            ull w1 = bcast2(WB[(e + 1) * HDIM + oh]);
            int ge = e0 + e;
#pragma unroll
            for (int p = 0; p < 8; p++) {
                ulonglong2 x2 = *(const ulonglong2*)&SH[p * 128 + ge];
                acc[p] = fma2(x2.x, w0, acc[p]);
                acc[p] = fma2(x2.y, w1, acc[p]);
            }
        }
    }

    const float bh = b1[oh];
    __syncthreads();   // all X reads done before H overwrite
#pragma unroll
    for (int p = 0; p < 8; p++) {
        float2 v = unpack2(acc[p]);
        SH[p * 256 + oh] = make_float2(fmaxf(v.x + bh, 0.f), fmaxf(v.y + bh, 0.f));
    }
    cpa_wait0();       // W2 chunk (gc=8) arrived
    __syncthreads();   // publish H

    // gemm2: each thread one (row, c); W2 in buffer 8%3=2
    const float* WB2 = ARENA + 2 * CHUNK_F;
    const int row = tid >> 4;          // 0..15
    const int c   = tid & (CDIM - 1);
    const int pr  = row >> 1, comp = row & 1;
    float sum = b2[c];
#pragma unroll 4
    for (int h = 0; h < HDIM; h += 2) {
        float2 h0 = SH[pr * 256 + h];
        float2 h1 = SH[pr * 256 + h + 1];
        float v0 = comp ? h0.y : h0.x;
        float v1 = comp ? h1.y : h1.x;
        sum = fmaf(v0, WB2[(h + 0) * CDIM + c], sum);
        sum = fmaf(v1, WB2[(h + 1) * CDIM + c], sum);
    }
    out[(row0 + row) * CDIM + c] = sum;
}

// ---------------------------------------------------------------------------
extern "C" void kernel_launch(void* const* d_in, const int* in_sizes, int n_in,
                              void* d_out, int out_size) {
    const int*   entity_ids = (const int*)d_in[0];
    const int*   module_ids = (const int*)d_in[1];
    const float* emb        = (const float*)d_in[2];
    const float* W_in       = (const float*)d_in[3];
    const float* b_in       = (const float*)d_in[4];
    const float* W_bias     = (const float*)d_in[5];
    const float* b_bias     = (const float*)d_in[6];
    const float* W_f        = (const float*)d_in[7];
    const float* b_f        = (const float*)d_in[8];
    const float* W1         = (const float*)d_in[9];
    const float* b1         = (const float*)d_in[10];
    const float* W2         = (const float*)d_in[11];
    const float* b2         = (const float*)d_in[12];
    float* out = (float*)d_out;

    cudaFuncSetAttribute(step_kernel, cudaFuncAttributeMaxDynamicSharedMemorySize, DYN_SMEM);
    cudaFuncSetAttribute(head_kernel, cudaFuncAttributeMaxDynamicSharedMemorySize, DYN_SMEM);

    setup_kernel<<<1, NTHR>>>(module_ids);
    for (int s = 0; s < NSTEPS; s++)
        step_kernel<<<MAX_TILES, NTHR, DYN_SMEM>>>(s, emb, entity_ids,
                                                   W_in, b_in, W_bias, b_bias, W_f, b_f);
    head_kernel<<<BB / RT, NTHR, DYN_SMEM>>>(W1, b1, W2, b2, out);
}

// round 8
// speedup vs baseline: 1.8483x; 1.8483x over previous
#include <cuda_runtime.h>
#include <cuda_bf16.h>
#include <math.h>
#include <stdint.h>

#define BB 4096
#define EE 128
#define MMOD 8
#define NSTEPS 3
#define HDIM 256
#define CDIM 16
#define TILE 64
#define NTHR 256
#define MAXT 72

#define S128B 272   // row stride (bytes) for K=128 bf16 images (128*2 + 16 pad)
#define S256B 528   // row stride for K=256 images

// step kernel smem offsets (bytes)
#define OXH 0
#define OXL 17408
#define OBH 34816
#define OBL 52224
#define OWIH 69632
#define OWIL 104448
#define OWBH 139264
#define OWBL 174080
#define STEP_SMEM 208896
// phase2 overlay
#define OHH 0
#define OHL 33792
#define OFH 69632
#define OFL 137216
// head kernel offsets
#define HXH 0
#define HXL 17408
#define HW1H 34816
#define HW1L 104448
#define HW2H 174080
#define HW2L 182528
#define HHH 0
#define HHL 33792
#define HEAD_SMEM 190976

// ---------------- global scratch (no allocation allowed) -------------------
__device__ uint32_t g_Xpair[2][BB * 64];   // state: packed bf16 (hi,lo) pairs
__device__ int g_order[NSTEPS * BB];
__device__ int g_tiles[NSTEPS * MAXT * 3];
// Transposed hi/lo-split pad-stride weight images
__device__ __align__(256) uint8_t g_WinT[2][MMOD * 34816];   // [o=128][e=128]
__device__ __align__(256) uint8_t g_WbiT[2][MMOD * 34816];
__device__ __align__(256) uint8_t g_WfT [2][MMOD * 67584];   // [o=128][f=256]
__device__ __align__(256) uint8_t g_W1T [2][69632];          // [j=256][e=128]
__device__ __align__(256) uint8_t g_W2T [2][8448];           // [c=16][j=256]

// ---------------- helpers ---------------------------------------------------
__device__ __forceinline__ uint32_t sptr(const void* p) {
    return (uint32_t)__cvta_generic_to_shared(p);
}
__device__ __forceinline__ void sts32(uint32_t a, uint32_t v) {
    asm volatile("st.shared.b32 [%0], %1;" :: "r"(a), "r"(v) : "memory");
}
__device__ __forceinline__ void cpa16(uint32_t s, const void* g) {
    asm volatile("cp.async.ca.shared.global [%0], [%1], 16;" :: "r"(s), "l"(g));
}
__device__ __forceinline__ void cpa_commit() { asm volatile("cp.async.commit_group;"); }
__device__ __forceinline__ void cpa_wait0()  { asm volatile("cp.async.wait_group 0;"); }
__device__ __forceinline__ void cpa_copy(uint32_t dst, const uint8_t* src, int bytes, int tid) {
    for (int off = tid * 16; off < bytes; off += NTHR * 16) cpa16(dst + off, src + off);
}
__device__ __forceinline__ void splitf(float v0, float v1, uint32_t& h, uint32_t& l) {
    __nv_bfloat16 h0 = __float2bfloat16(v0), h1 = __float2bfloat16(v1);
    float r0 = v0 - __bfloat162float(h0), r1 = v1 - __bfloat162float(h1);
    __nv_bfloat16 l0 = __float2bfloat16(r0), l1 = __float2bfloat16(r1);
    h = (uint32_t)__bfloat16_as_ushort(h0) | ((uint32_t)__bfloat16_as_ushort(h1) << 16);
    l = (uint32_t)__bfloat16_as_ushort(l0) | ((uint32_t)__bfloat16_as_ushort(l1) << 16);
}
__device__ __forceinline__ void ldsm4(uint32_t* a, uint32_t addr) {
    asm volatile("ldmatrix.sync.aligned.m8n8.x4.shared.b16 {%0,%1,%2,%3}, [%4];"
                 : "=r"(a[0]), "=r"(a[1]), "=r"(a[2]), "=r"(a[3]) : "r"(addr));
}
__device__ __forceinline__ void ldsm2(uint32_t& b0, uint32_t& b1, uint32_t addr) {
    asm volatile("ldmatrix.sync.aligned.m8n8.x2.shared.b16 {%0,%1}, [%2];"
                 : "=r"(b0), "=r"(b1) : "r"(addr));
}
__device__ __forceinline__ void mma4(float* c, const uint32_t* a, uint32_t b0, uint32_t b1) {
    asm volatile("mma.sync.aligned.m16n8k16.row.col.f32.bf16.bf16.f32 "
                 "{%0,%1,%2,%3},{%4,%5,%6,%7},{%8,%9},{%0,%1,%2,%3};"
                 : "+f"(c[0]), "+f"(c[1]), "+f"(c[2]), "+f"(c[3])
                 : "r"(a[0]), "r"(a[1]), "r"(a[2]), "r"(a[3]), "r"(b0), "r"(b1));
}

// Warp GEMM: acc[2][NT][4] over M-stripes {mbase, mbase+16}, N-tiles nbase+8*nt.
// 3-term hi/lo split: Ah*Bh + Ah*Bl + Al*Bh.
template<int NT, int KS, int SBA, int SBB>
__device__ __forceinline__ void wgemm(float* acc,
                                      uint32_t aHI, uint32_t aLO,
                                      uint32_t bHI, uint32_t bLO,
                                      int mbase, int nbase, int lane) {
    const uint32_t aoff = (uint32_t)(mbase + (lane & 15)) * SBA + ((lane >> 4) * 16);
    const uint32_t boff = (uint32_t)(nbase + (lane & 7)) * SBB + (((lane >> 3) & 1) * 16);
#pragma unroll
    for (int term = 0; term < 3; term++) {
        uint32_t A = ((term == 2) ? aLO : aHI) + aoff;
        uint32_t B = ((term == 1) ? bLO : bHI) + boff;
#pragma unroll
        for (int k = 0; k < KS; k++) {
            uint32_t a0[4], a1[4];
            ldsm4(a0, A + k * 32);
            ldsm4(a1, A + 16 * SBA + k * 32);
#pragma unroll
            for (int nt = 0; nt < NT; nt++) {
                uint32_t b0, b1;
                ldsm2(b0, b1, B + nt * 8 * SBB + k * 32);
                mma4(acc + (0 * NT + nt) * 4, a0, b0, b1);
                mma4(acc + (1 * NT + nt) * 4, a1, b0, b1);
            }
        }
    }
}

// ---------------------------------------------------------------------------
__global__ void setup_kernel(const int* __restrict__ module_ids) {
    __shared__ int cnt[MMOD], cur[MMOD];
    int tid = threadIdx.x;
    for (int s = 0; s < NSTEPS; s++) {
        if (tid < MMOD) cnt[tid] = 0;
        __syncthreads();
        for (int b = tid; b < BB; b += NTHR)
            atomicAdd(&cnt[module_ids[b * NSTEPS + s]], 1);
        __syncthreads();
        if (tid == 0) {
            int o = 0, t = 0;
            for (int m = 0; m < MMOD; m++) {
                cur[m] = o;
                int c = cnt[m];
                for (int ch = 0; ch < c; ch += TILE) {
                    g_tiles[(s * MAXT + t) * 3 + 0] = m;
                    g_tiles[(s * MAXT + t) * 3 + 1] = o + ch;
                    g_tiles[(s * MAXT + t) * 3 + 2] = min(TILE, c - ch);
                    t++;
                }
                o += c;
            }
            for (; t < MAXT; t++) g_tiles[(s * MAXT + t) * 3 + 2] = 0;
        }
        __syncthreads();
        for (int b = tid; b < BB; b += NTHR) {
            int m = module_ids[b * NSTEPS + s];
            int p = atomicAdd(&cur[m], 1);
            g_order[s * BB + p] = b;
        }
        __syncthreads();
    }
}

// Build transposed hi/lo-split pad-stride weight images.
__global__ void xform_kernel(const float* __restrict__ W_in,
                             const float* __restrict__ W_bias,
                             const float* __restrict__ W_f,
                             const float* __restrict__ W1,
                             const float* __restrict__ W2) {
    int j = blockIdx.y;
    const float* src; uint8_t *dh, *dl; int R, C, SB;
    if (j < 8)       { src = W_in + j * 16384;  dh = g_WinT[0] + j * 34816; dl = g_WinT[1] + j * 34816; R = 128; C = 128; SB = S128B; }
    else if (j < 16) { int q = j - 8;  src = W_bias + q * 16384; dh = g_WbiT[0] + q * 34816; dl = g_WbiT[1] + q * 34816; R = 128; C = 128; SB = S128B; }
    else if (j < 24) { int q = j - 16; src = W_f + q * 32768;    dh = g_WfT[0] + q * 67584;  dl = g_WfT[1] + q * 67584;  R = 128; C = 256; SB = S256B; }
    else if (j == 24){ src = W1; dh = g_W1T[0]; dl = g_W1T[1]; R = 256; C = 128; SB = S128B; }
    else             { src = W2; dh = g_W2T[0]; dl = g_W2T[1]; R = 16;  C = 256; SB = S256B; }
    int units = R * C / 2;
    for (int u = blockIdx.x * NTHR + threadIdx.x; u < units; u += gridDim.x * NTHR) {
        int rr = u % R, cc = (u / R) * 2;
        float v0 = src[(size_t)cc * R + rr];
        float v1 = src[(size_t)(cc + 1) * R + rr];
        uint32_t h, l;
        splitf(v0, v1, h, l);
        *(uint32_t*)(dh + (size_t)rr * SB + cc * 2) = h;
        *(uint32_t*)(dl + (size_t)rr * SB + cc * 2) = l;
    }
}

// ---------------------------------------------------------------------------
// Step: one (module, 64-row tile); all GEMMs via mma.sync bf16 3-term split.
// ---------------------------------------------------------------------------
__global__ __launch_bounds__(NTHR)
void step_kernel(int s, const float* __restrict__ emb, const int* __restrict__ eids,
                 const float* __restrict__ b_in, const float* __restrict__ b_bias,
                 const float* __restrict__ b_f) {
    extern __shared__ uint8_t raw[];
    const uint32_t base = sptr(raw);
    __shared__ int ridx[TILE], xsrc[TILE], eidn[TILE];
    __shared__ float sbi[EE], sbb[EE], sbf[EE];
    int tid = threadIdx.x, wid = tid >> 5, lane = tid & 31;
    int t = blockIdx.x;

    int m   = g_tiles[(s * MAXT + t) * 3 + 0];
    int bse = g_tiles[(s * MAXT + t) * 3 + 1];
    int cnt = g_tiles[(s * MAXT + t) * 3 + 2];
    if (cnt == 0) return;

    if (tid < TILE) {
        int row = g_order[s * BB + bse + (tid < cnt ? tid : 0)];
        ridx[tid] = row;
        xsrc[tid] = (s == 0) ? eids[row * (NSTEPS + 1)] : row;
        eidn[tid] = eids[row * (NSTEPS + 1) + s + 1];
    }
    if (tid < EE) { sbi[tid] = b_in[m*EE+tid]; sbb[tid] = b_bias[m*EE+tid]; sbf[tid] = b_f[m*EE+tid]; }

    // stage Wi, Wb (hi/lo)
    cpa_copy(base + OWIH, g_WinT[0] + m * 34816, 34816, tid);
    cpa_copy(base + OWIL, g_WinT[1] + m * 34816, 34816, tid);
    cpa_copy(base + OWBH, g_WbiT[0] + m * 34816, 34816, tid);
    cpa_copy(base + OWBL, g_WbiT[1] + m * 34816, 34816, tid);
    cpa_commit();
    __syncthreads();   // ridx/eidn visible

    // gather X and Bias tiles into images
    for (int i = tid; i < TILE * 64; i += NTHR) {
        int r = i >> 6, k = i & 63;
        uint32_t h, l;
        if (s == 0) {
            float2 v = *(const float2*)&emb[(size_t)xsrc[r] * EE + 2 * k];
            splitf(v.x, v.y, h, l);
        } else {
            h = g_Xpair[0][xsrc[r] * 64 + k];
            l = g_Xpair[1][xsrc[r] * 64 + k];
        }
        sts32(base + OXH + r * S128B + k * 4, h);
        sts32(base + OXL + r * S128B + k * 4, l);
        float2 bv = *(const float2*)&emb[(size_t)eidn[r] * EE + 2 * k];
        splitf(bv.x, bv.y, h, l);
        sts32(base + OBH + r * S128B + k * 4, h);
        sts32(base + OBL + r * S128B + k * 4, l);
    }
    cpa_wait0();
    __syncthreads();

    const int mh = wid >> 2, nq = wid & 3;
    const int g = lane >> 2, cp = (lane & 3) * 2;

    float acc1[2 * 4 * 4], acc2[2 * 4 * 4];
#pragma unroll
    for (int i = 0; i < 32; i++) { acc1[i] = 0.f; acc2[i] = 0.f; }
    wgemm<4, 8, S128B, S128B>(acc1, base + OXH, base + OXL, base + OWIH, base + OWIL,
                              mh * 32, nq * 32, lane);
    wgemm<4, 8, S128B, S128B>(acc2, base + OBH, base + OBL, base + OWBH, base + OWBL,
                              mh * 32, nq * 32, lane);
    __syncthreads();   // all fragment reads done; safe to overwrite

    // stage Wf while writing H
    cpa_copy(base + OFH, g_WfT[0] + m * 67584, 67584, tid);
    cpa_copy(base + OFL, g_WfT[1] + m * 67584, 67584, tid);
    cpa_commit();

    // H = [relu(D1+b_in) | relu(D2+b_bias)] as hi/lo images [64][256]
#pragma unroll
    for (int ms = 0; ms < 2; ms++)
#pragma unroll
        for (int nt = 0; nt < 4; nt++) {
            int r0 = mh * 32 + ms * 16 + g;
            int cw = nq * 32 + nt * 8 + cp;
            float* c1 = acc1 + (ms * 4 + nt) * 4;
            float* c2 = acc2 + (ms * 4 + nt) * 4;
            uint32_t h, l;
            splitf(fmaxf(c1[0] + sbi[cw], 0.f), fmaxf(c1[1] + sbi[cw + 1], 0.f), h, l);
            sts32(base + OHH + r0 * S256B + cw * 2, h);
            sts32(base + OHL + r0 * S256B + cw * 2, l);
            splitf(fmaxf(c1[2] + sbi[cw], 0.f), fmaxf(c1[3] + sbi[cw + 1], 0.f), h, l);
            sts32(base + OHH + (r0 + 8) * S256B + cw * 2, h);
            sts32(base + OHL + (r0 + 8) * S256B + cw * 2, l);
            splitf(fmaxf(c2[0] + sbb[cw], 0.f), fmaxf(c2[1] + sbb[cw + 1], 0.f), h, l);
            sts32(base + OHH + r0 * S256B + 256 + cw * 2, h);
            sts32(base + OHL + r0 * S256B + 256 + cw * 2, l);
            splitf(fmaxf(c2[2] + sbb[cw], 0.f), fmaxf(c2[3] + sbb[cw + 1], 0.f), h, l);
            sts32(base + OHH + (r0 + 8) * S256B + 256 + cw * 2, h);
            sts32(base + OHL + (r0 + 8) * S256B + 256 + cw * 2, l);
        }
    cpa_wait0();
    __syncthreads();

    float acc3[2 * 4 * 4];
#pragma unroll
    for (int i = 0; i < 32; i++) acc3[i] = 0.f;
    wgemm<4, 16, S256B, S256B>(acc3, base + OHH, base + OHL, base + OFH, base + OFL,
                               mh * 32, nq * 32, lane);

    // x' = tanh(D3 + b_f) -> g_Xpair
#pragma unroll
    for (int ms = 0; ms < 2; ms++)
#pragma unroll
        for (int nt = 0; nt < 4; nt++) {
            int r0 = mh * 32 + ms * 16 + g;
            int cw = nq * 32 + nt * 8 + cp;
            float* c = acc3 + (ms * 4 + nt) * 4;
            uint32_t h, l;
            if (r0 < cnt) {
                int gr = ridx[r0];
                splitf(tanhf(c[0] + sbf[cw]), tanhf(c[1] + sbf[cw + 1]), h, l);
                g_Xpair[0][gr * 64 + (cw >> 1)] = h;
                g_Xpair[1][gr * 64 + (cw >> 1)] = l;
            }
            if (r0 + 8 < cnt) {
                int gr = ridx[r0 + 8];
                splitf(tanhf(c[2] + sbf[cw]), tanhf(c[3] + sbf[cw + 1]), h, l);
                g_Xpair[0][gr * 64 + (cw >> 1)] = h;
                g_Xpair[1][gr * 64 + (cw >> 1)] = l;
            }
        }
}

// ---------------------------------------------------------------------------
// Head: out = relu(X @ W1 + b1) @ W2 + b2 per 64-row tile.
// ---------------------------------------------------------------------------
__global__ __launch_bounds__(NTHR)
void head_kernel(const float* __restrict__ b1, const float* __restrict__ b2,
                 float* __restrict__ out) {
    extern __shared__ uint8_t raw[];
    const uint32_t base = sptr(raw);
    __shared__ float sb1[HDIM], sb2[CDIM];
    int tid = threadIdx.x, wid = tid >> 5, lane = tid & 31;
    int row0 = blockIdx.x * TILE;

    if (tid < HDIM) sb1[tid] = b1[tid];
    if (tid < CDIM) sb2[tid] = b2[tid];
    cpa_copy(base + HW1H, g_W1T[0], 69632, tid);
    cpa_copy(base + HW1L, g_W1T[1], 69632, tid);
    cpa_copy(base + HW2H, g_W2T[0], 8448, tid);
    cpa_copy(base + HW2L, g_W2T[1], 8448, tid);
    cpa_commit();

    for (int i = tid; i < TILE * 64; i += NTHR) {
        int r = i >> 6, k = i & 63;
        sts32(base + HXH + r * S128B + k * 4, g_Xpair[0][(row0 + r) * 64 + k]);
        sts32(base + HXL + r * S128B + k * 4, g_Xpair[1][(row0 + r) * 64 + k]);
    }
    cpa_wait0();
    __syncthreads();

    const int mh = wid >> 2, nq = wid & 3;
    const int g = lane >> 2, cp = (lane & 3) * 2;

    float acc[2 * 8 * 4];
#pragma unroll
    for (int i = 0; i < 64; i++) acc[i] = 0.f;
    wgemm<8, 8, S128B, S128B>(acc, base + HXH, base + HXL, base + HW1H, base + HW1L,
                              mh * 32, nq * 64, lane);
    __syncthreads();   // X/W1 reads done before H overwrite

#pragma unroll
    for (int ms = 0; ms < 2; ms++)
#pragma unroll
        for (int nt = 0; nt < 8; nt++) {
            int r0 = mh * 32 + ms * 16 + g;
            int cw = nq * 64 + nt * 8 + cp;
            float* c = acc + (ms * 8 + nt) * 4;
            uint32_t h, l;
            splitf(fmaxf(c[0] + sb1[cw], 0.f), fmaxf(c[1] + sb1[cw + 1], 0.f), h, l);
            sts32(base + HHH + r0 * S256B + cw * 2, h);
            sts32(base + HHL + r0 * S256B + cw * 2, l);
            splitf(fmaxf(c[2] + sb1[cw], 0.f), fmaxf(c[3] + sb1[cw + 1], 0.f), h, l);
            sts32(base + HHH + (r0 + 8) * S256B + cw * 2, h);
            sts32(base + HHL + (r0 + 8) * S256B + cw * 2, l);
        }
    __syncthreads();

    if ((wid & 3) < 2) {
        int n0 = (wid & 3) * 8;
        float acc2[2 * 1 * 4];
#pragma unroll
        for (int i = 0; i < 8; i++) acc2[i] = 0.f;
        wgemm<1, 16, S256B, S256B>(acc2, base + HHH, base + HHL, base + HW2H, base + HW2L,
                                   mh * 32, n0, lane);
#pragma unroll
        for (int ms = 0; ms < 2; ms++) {
            int r = row0 + mh * 32 + ms * 16 + g;
            float* c = acc2 + ms * 4;
            out[r * CDIM + n0 + cp]           = c[0] + sb2[n0 + cp];
            out[r * CDIM + n0 + cp + 1]       = c[1] + sb2[n0 + cp + 1];
            out[(r + 8) * CDIM + n0 + cp]     = c[2] + sb2[n0 + cp];
            out[(r + 8) * CDIM + n0 + cp + 1] = c[3] + sb2[n0 + cp + 1];
        }
    }
}

// ---------------------------------------------------------------------------
extern "C" void kernel_launch(void* const* d_in, const int* in_sizes, int n_in,
                              void* d_out, int out_size) {
    const int*   entity_ids = (const int*)d_in[0];
    const int*   module_ids = (const int*)d_in[1];
    const float* emb        = (const float*)d_in[2];
    const float* W_in       = (const float*)d_in[3];
    const float* b_in       = (const float*)d_in[4];
    const float* W_bias     = (const float*)d_in[5];
    const float* b_bias     = (const float*)d_in[6];
    const float* W_f        = (const float*)d_in[7];
    const float* b_f        = (const float*)d_in[8];
    const float* W1         = (const float*)d_in[9];
    const float* b1         = (const float*)d_in[10];
    const float* W2         = (const float*)d_in[11];
    const float* b2         = (const float*)d_in[12];
    float* out = (float*)d_out;

    cudaFuncSetAttribute(step_kernel, cudaFuncAttributeMaxDynamicSharedMemorySize, STEP_SMEM);
    cudaFuncSetAttribute(head_kernel, cudaFuncAttributeMaxDynamicSharedMemorySize, HEAD_SMEM);

    setup_kernel<<<1, NTHR>>>(module_ids);
    xform_kernel<<<dim3(32, 26), NTHR>>>(W_in, W_bias, W_f, W1, W2);
    for (int s = 0; s < NSTEPS; s++)
        step_kernel<<<MAXT, NTHR, STEP_SMEM>>>(s, emb, entity_ids, b_in, b_bias, b_f);
    head_kernel<<<BB / TILE, NTHR, HEAD_SMEM>>>(b1, b2, out);
}

// round 9
// speedup vs baseline: 2.5087x; 1.3573x over previous
#include <cuda_runtime.h>
#include <cuda_bf16.h>
#include <math.h>
#include <stdint.h>

#define BB 4096
#define EE 128
#define MMOD 8
#define NSTEPS 3
#define HDIM 256
#define CDIM 16
#define TILE 64
#define NTHR 256
#define MAXT 72

#define S128B 272   // row stride (bytes), K=128 bf16 images
#define S256B 528   // row stride, K=256 images
#define HIMG  33792 // one 64x256 bf16 image (64*528)

// P1 smem: A hi/lo + W hi/lo
#define P1_AH 0
#define P1_AL 17408
#define P1_WH 34816
#define P1_WL 69632
#define P1_SMEM 104448
// P2 smem: H hi/lo + Wf-half hi/lo
#define P2_HH 0
#define P2_HL 33792
#define P2_WH 67584
#define P2_WL 101376
#define P2_SMEM 135168
// head P2 smem
#define HP2_HH 0
#define HP2_HL 33792
#define HP2_WH 67584
#define HP2_WL 76032
#define HP2_SMEM 84480

// ---------------- global scratch ------------------------------------------
__device__ uint32_t g_Xpair[2][BB * 64];            // state: packed bf16 hi/lo
__device__ int g_order[NSTEPS * BB];
__device__ int g_tiles[NSTEPS * MAXT * 3];
__device__ __align__(256) uint8_t g_Himg[2][MAXT * HIMG];   // per-tile H images
// Transposed hi/lo-split pad-stride weight images
__device__ __align__(256) uint8_t g_WinT[2][MMOD * 34816];  // [o=128][e=128]
__device__ __align__(256) uint8_t g_WbiT[2][MMOD * 34816];
__device__ __align__(256) uint8_t g_WfT [2][MMOD * 67584];  // [o=128][f=256]
__device__ __align__(256) uint8_t g_W1T [2][69632];         // [j=256][e=128]
__device__ __align__(256) uint8_t g_W2T [2][8448];          // [c=16][j=256]

// ---------------- helpers ---------------------------------------------------
__device__ __forceinline__ uint32_t sptr(const void* p) {
    return (uint32_t)__cvta_generic_to_shared(p);
}
__device__ __forceinline__ void sts32(uint32_t a, uint32_t v) {
    asm volatile("st.shared.b32 [%0], %1;" :: "r"(a), "r"(v) : "memory");
}
__device__ __forceinline__ void cpa16(uint32_t s, const void* g) {
    asm volatile("cp.async.ca.shared.global [%0], [%1], 16;" :: "r"(s), "l"(g));
}
__device__ __forceinline__ void cpa_commit() { asm volatile("cp.async.commit_group;"); }
__device__ __forceinline__ void cpa_wait0()  { asm volatile("cp.async.wait_group 0;"); }
__device__ __forceinline__ void cpa_copy(uint32_t dst, const uint8_t* src, int bytes, int tid) {
    for (int off = tid * 16; off < bytes; off += NTHR * 16) cpa16(dst + off, src + off);
}
__device__ __forceinline__ void splitf(float v0, float v1, uint32_t& h, uint32_t& l) {
    __nv_bfloat16 h0 = __float2bfloat16(v0), h1 = __float2bfloat16(v1);
    float r0 = v0 - __bfloat162float(h0), r1 = v1 - __bfloat162float(h1);
    __nv_bfloat16 l0 = __float2bfloat16(r0), l1 = __float2bfloat16(r1);
    h = (uint32_t)__bfloat16_as_ushort(h0) | ((uint32_t)__bfloat16_as_ushort(h1) << 16);
    l = (uint32_t)__bfloat16_as_ushort(l0) | ((uint32_t)__bfloat16_as_ushort(l1) << 16);
}
__device__ __forceinline__ void ldsm4(uint32_t* a, uint32_t addr) {
    asm volatile("ldmatrix.sync.aligned.m8n8.x4.shared.b16 {%0,%1,%2,%3}, [%4];"
                 : "=r"(a[0]), "=r"(a[1]), "=r"(a[2]), "=r"(a[3]) : "r"(addr));
}
__device__ __forceinline__ void ldsm2(uint32_t& b0, uint32_t& b1, uint32_t addr) {
    asm volatile("ldmatrix.sync.aligned.m8n8.x2.shared.b16 {%0,%1}, [%2];"
                 : "=r"(b0), "=r"(b1) : "r"(addr));
}
__device__ __forceinline__ void mma4(float* c, const uint32_t* a, uint32_t b0, uint32_t b1) {
    asm volatile("mma.sync.aligned.m16n8k16.row.col.f32.bf16.bf16.f32 "
                 "{%0,%1,%2,%3},{%4,%5,%6,%7},{%8,%9},{%0,%1,%2,%3};"
                 : "+f"(c[0]), "+f"(c[1]), "+f"(c[2]), "+f"(c[3])
                 : "r"(a[0]), "r"(a[1]), "r"(a[2]), "r"(a[3]), "r"(b0), "r"(b1));
}
// Warp GEMM, 3-term hi/lo split. acc[2][NT][4]; M stripes mbase, mbase+16.
template<int NT, int KS, int SBA, int SBB>
__device__ __forceinline__ void wgemm(float* acc,
                                      uint32_t aHI, uint32_t aLO,
                                      uint32_t bHI, uint32_t bLO,
                                      int mbase, int nbase, int lane) {
    const uint32_t aoff = (uint32_t)(mbase + (lane & 15)) * SBA + ((lane >> 4) * 16);
    const uint32_t boff = (uint32_t)(nbase + (lane & 7)) * SBB + (((lane >> 3) & 1) * 16);
#pragma unroll
    for (int term = 0; term < 3; term++) {
        uint32_t A = ((term == 2) ? aLO : aHI) + aoff;
        uint32_t B = ((term == 1) ? bLO : bHI) + boff;
#pragma unroll
        for (int k = 0; k < KS; k++) {
            uint32_t a0[4], a1[4];
            ldsm4(a0, A + k * 32);
            ldsm4(a1, A + 16 * SBA + k * 32);
#pragma unroll
            for (int nt = 0; nt < NT; nt++) {
                uint32_t b0, b1;
                ldsm2(b0, b1, B + nt * 8 * SBB + k * 32);
                mma4(acc + (0 * NT + nt) * 4, a0, b0, b1);
                mma4(acc + (1 * NT + nt) * 4, a1, b0, b1);
            }
        }
    }
}

// ---------------------------------------------------------------------------
__global__ void setup_kernel(const int* __restrict__ module_ids) {
    __shared__ int cnt[MMOD], cur[MMOD];
    int tid = threadIdx.x, s = blockIdx.x;
    if (tid < MMOD) cnt[tid] = 0;
    __syncthreads();
    for (int b = tid; b < BB; b += NTHR)
        atomicAdd(&cnt[module_ids[b * NSTEPS + s]], 1);
    __syncthreads();
    if (tid == 0) {
        int o = 0, t = 0;
        for (int m = 0; m < MMOD; m++) {
            cur[m] = o;
            int c = cnt[m];
            for (int ch = 0; ch < c; ch += TILE) {
                g_tiles[(s * MAXT + t) * 3 + 0] = m;
                g_tiles[(s * MAXT + t) * 3 + 1] = o + ch;
                g_tiles[(s * MAXT + t) * 3 + 2] = min(TILE, c - ch);
                t++;
            }
            o += c;
        }
        for (; t < MAXT; t++) g_tiles[(s * MAXT + t) * 3 + 2] = 0;
    }
    __syncthreads();
    for (int b = tid; b < BB; b += NTHR) {
        int m = module_ids[b * NSTEPS + s];
        int p = atomicAdd(&cur[m], 1);
        g_order[s * BB + p] = b;
    }
}

// Build transposed hi/lo-split pad-stride weight images.
__global__ void xform_kernel(const float* __restrict__ W_in,
                             const float* __restrict__ W_bias,
                             const float* __restrict__ W_f,
                             const float* __restrict__ W1,
                             const float* __restrict__ W2) {
    int j = blockIdx.y;
    const float* src; uint8_t *dh, *dl; int R, C, SB;
    if (j < 8)       { src = W_in + j * 16384;  dh = g_WinT[0] + j * 34816; dl = g_WinT[1] + j * 34816; R = 128; C = 128; SB = S128B; }
    else if (j < 16) { int q = j - 8;  src = W_bias + q * 16384; dh = g_WbiT[0] + q * 34816; dl = g_WbiT[1] + q * 34816; R = 128; C = 128; SB = S128B; }
    else if (j < 24) { int q = j - 16; src = W_f + q * 32768;    dh = g_WfT[0] + q * 67584;  dl = g_WfT[1] + q * 67584;  R = 128; C = 256; SB = S256B; }
    else if (j == 24){ src = W1; dh = g_W1T[0]; dl = g_W1T[1]; R = 256; C = 128; SB = S128B; }
    else             { src = W2; dh = g_W2T[0]; dl = g_W2T[1]; R = 16;  C = 256; SB = S256B; }
    int units = R * C / 2;
    for (int u = blockIdx.x * NTHR + threadIdx.x; u < units; u += gridDim.x * NTHR) {
        int rr = u % R, cc = (u / R) * 2;
        float v0 = src[(size_t)cc * R + rr];
        float v1 = src[(size_t)(cc + 1) * R + rr];
        uint32_t h, l;
        splitf(v0, v1, h, l);
        *(uint32_t*)(dh + (size_t)rr * SB + cc * 2) = h;
        *(uint32_t*)(dl + (size_t)rr * SB + cc * 2) = l;
    }
}

// ---------------------------------------------------------------------------
// Step P1: CTA = (tile, half). half 0: Hin = relu(X@Wi+bi); half 1: Hbi.
// Writes its 128 columns of the tile's H image.
// ---------------------------------------------------------------------------
__global__ __launch_bounds__(NTHR)
void step_p1(int s, const float* __restrict__ emb, const int* __restrict__ eids,
             const float* __restrict__ b_in, const float* __restrict__ b_bias) {
    extern __shared__ uint8_t raw[];
    const uint32_t base = sptr(raw);
    __shared__ int srow[TILE];
    __shared__ float sb[EE];
    int tid = threadIdx.x, wid = tid >> 5, lane = tid & 31;
    int t = blockIdx.x >> 1, h = blockIdx.x & 1;

    int m   = g_tiles[(s * MAXT + t) * 3 + 0];
    int bse = g_tiles[(s * MAXT + t) * 3 + 1];
    int cnt = g_tiles[(s * MAXT + t) * 3 + 2];
    if (cnt == 0) return;

    const uint8_t* WH = (h ? g_WbiT[0] : g_WinT[0]) + m * 34816;
    const uint8_t* WL = (h ? g_WbiT[1] : g_WinT[1]) + m * 34816;
    cpa_copy(base + P1_WH, WH, 34816, tid);
    cpa_copy(base + P1_WL, WL, 34816, tid);
    cpa_commit();

    if (tid < TILE) {
        int row = g_order[s * BB + bse + (tid < cnt ? tid : 0)];
        srow[tid] = h ? eids[row * (NSTEPS + 1) + s + 1]
                      : ((s == 0) ? eids[row * (NSTEPS + 1)] : row);
    }
    if (tid < EE) sb[tid] = h ? b_bias[m * EE + tid] : b_in[m * EE + tid];
    __syncthreads();

    const bool frompair = (h == 0 && s > 0);
    for (int i = tid; i < TILE * 64; i += NTHR) {
        int r = i >> 6, k = i & 63;
        uint32_t hh, ll;
        if (frompair) {
            hh = g_Xpair[0][srow[r] * 64 + k];
            ll = g_Xpair[1][srow[r] * 64 + k];
        } else {
            float2 v = *(const float2*)&emb[(size_t)srow[r] * EE + 2 * k];
            splitf(v.x, v.y, hh, ll);
        }
        sts32(base + P1_AH + r * S128B + k * 4, hh);
        sts32(base + P1_AL + r * S128B + k * 4, ll);
    }
    cpa_wait0();
    __syncthreads();

    const int mh = wid >> 2, nq = wid & 3;
    const int g = lane >> 2, cp = (lane & 3) * 2;
    float acc[2 * 4 * 4];
#pragma unroll
    for (int i = 0; i < 32; i++) acc[i] = 0.f;
    wgemm<4, 8, S128B, S128B>(acc, base + P1_AH, base + P1_AL,
                              base + P1_WH, base + P1_WL, mh * 32, nq * 32, lane);

    uint8_t* HD0 = g_Himg[0] + t * HIMG + h * 256;   // col offset h*128 cols * 2B
    uint8_t* HD1 = g_Himg[1] + t * HIMG + h * 256;
#pragma unroll
    for (int ms = 0; ms < 2; ms++)
#pragma unroll
        for (int nt = 0; nt < 4; nt++) {
            int r0 = mh * 32 + ms * 16 + g;
            int cw = nq * 32 + nt * 8 + cp;
            float* c = acc + (ms * 4 + nt) * 4;
            uint32_t hh, ll;
            splitf(fmaxf(c[0] + sb[cw], 0.f), fmaxf(c[1] + sb[cw + 1], 0.f), hh, ll);
            *(uint32_t*)(HD0 + (size_t)r0 * S256B + cw * 2) = hh;
            *(uint32_t*)(HD1 + (size_t)r0 * S256B + cw * 2) = ll;
            splitf(fmaxf(c[2] + sb[cw], 0.f), fmaxf(c[3] + sb[cw + 1], 0.f), hh, ll);
            *(uint32_t*)(HD0 + (size_t)(r0 + 8) * S256B + cw * 2) = hh;
            *(uint32_t*)(HD1 + (size_t)(r0 + 8) * S256B + cw * 2) = ll;
        }
}

// ---------------------------------------------------------------------------
// Step P2: CTA = (tile, N-half). x'[:, nh*64:+64] = tanh(H @ WfT_half + b_f).
// ---------------------------------------------------------------------------
__global__ __launch_bounds__(NTHR)
void step_p2(int s, const float* __restrict__ b_f) {
    extern __shared__ uint8_t raw[];
    const uint32_t base = sptr(raw);
    __shared__ int ridx[TILE];
    __shared__ float sb[TILE];
    int tid = threadIdx.x, wid = tid >> 5, lane = tid & 31;
    int t = blockIdx.x >> 1, nh = blockIdx.x & 1;

    int m   = g_tiles[(s * MAXT + t) * 3 + 0];
    int bse = g_tiles[(s * MAXT + t) * 3 + 1];
    int cnt = g_tiles[(s * MAXT + t) * 3 + 2];
    if (cnt == 0) return;

    cpa_copy(base + P2_HH, g_Himg[0] + t * HIMG, HIMG, tid);
    cpa_copy(base + P2_HL, g_Himg[1] + t * HIMG, HIMG, tid);
    cpa_copy(base + P2_WH, g_WfT[0] + m * 67584 + nh * 33792, 33792, tid);
    cpa_copy(base + P2_WL, g_WfT[1] + m * 67584 + nh * 33792, 33792, tid);
    cpa_commit();

    if (tid < TILE) {
        ridx[tid] = g_order[s * BB + bse + (tid < cnt ? tid : 0)];
        sb[tid] = b_f[m * EE + nh * 64 + tid];
    }
    cpa_wait0();
    __syncthreads();

    const int mh = wid >> 2, nq = wid & 3;
    const int g = lane >> 2, cp = (lane & 3) * 2;
    float acc[2 * 2 * 4];
#pragma unroll
    for (int i = 0; i < 16; i++) acc[i] = 0.f;
    wgemm<2, 16, S256B, S256B>(acc, base + P2_HH, base + P2_HL,
                               base + P2_WH, base + P2_WL, mh * 32, nq * 16, lane);

#pragma unroll
    for (int ms = 0; ms < 2; ms++)
#pragma unroll
        for (int nt = 0; nt < 2; nt++) {
            int r0 = mh * 32 + ms * 16 + g;
            int cl = nq * 16 + nt * 8 + cp;        // local col 0..63
            int cg = nh * 64 + cl;                 // global feature col
            float* c = acc + (ms * 2 + nt) * 4;
            uint32_t hh, ll;
            if (r0 < cnt) {
                int gr = ridx[r0];
                splitf(tanhf(c[0] + sb[cl]), tanhf(c[1] + sb[cl + 1]), hh, ll);
                g_Xpair[0][gr * 64 + (cg >> 1)] = hh;
                g_Xpair[1][gr * 64 + (cg >> 1)] = ll;
            }
            if (r0 + 8 < cnt) {
                int gr = ridx[r0 + 8];
                splitf(tanhf(c[2] + sb[cl]), tanhf(c[3] + sb[cl + 1]), hh, ll);
                g_Xpair[0][gr * 64 + (cg >> 1)] = hh;
                g_Xpair[1][gr * 64 + (cg >> 1)] = ll;
            }
        }
}

// ---------------------------------------------------------------------------
// Head P1: CTA = (tile, j-half). H[:, h*128:+128] = relu(X @ W1T_half + b1).
// ---------------------------------------------------------------------------
__global__ __launch_bounds__(NTHR)
void head_p1(const float* __restrict__ b1) {
    extern __shared__ uint8_t raw[];
    const uint32_t base = sptr(raw);
    __shared__ float sb[EE];
    int tid = threadIdx.x, wid = tid >> 5, lane = tid & 31;
    int t = blockIdx.x >> 1, h = blockIdx.x & 1;
    int row0 = t * TILE;

    cpa_copy(base + P1_WH, g_W1T[0] + h * 34816, 34816, tid);
    cpa_copy(base + P1_WL, g_W1T[1] + h * 34816, 34816, tid);
    cpa_commit();
    if (tid < EE) sb[tid] = b1[h * EE + tid];

    for (int i = tid; i < TILE * 64; i += NTHR) {
        int r = i >> 6, k = i & 63;
        sts32(base + P1_AH + r * S128B + k * 4, g_Xpair[0][(row0 + r) * 64 + k]);
        sts32(base + P1_AL + r * S128B + k * 4, g_Xpair[1][(row0 + r) * 64 + k]);
    }
    cpa_wait0();
    __syncthreads();

    const int mh = wid >> 2, nq = wid & 3;
    const int g = lane >> 2, cp = (lane & 3) * 2;
    float acc[2 * 4 * 4];
#pragma unroll
    for (int i = 0; i < 32; i++) acc[i] = 0.f;
    wgemm<4, 8, S128B, S128B>(acc, base + P1_AH, base + P1_AL,
                              base + P1_WH, base + P1_WL, mh * 32, nq * 32, lane);

    uint8_t* HD0 = g_Himg[0] + t * HIMG + h * 256;
    uint8_t* HD1 = g_Himg[1] + t * HIMG + h * 256;
#pragma unroll
    for (int ms = 0; ms < 2; ms++)
#pragma unroll
        for (int nt = 0; nt < 4; nt++) {
            int r0 = mh * 32 + ms * 16 + g;
            int cw = nq * 32 + nt * 8 + cp;
            float* c = acc + (ms * 4 + nt) * 4;
            uint32_t hh, ll;
            splitf(fmaxf(c[0] + sb[cw], 0.f), fmaxf(c[1] + sb[cw + 1], 0.f), hh, ll);
            *(uint32_t*)(HD0 + (size_t)r0 * S256B + cw * 2) = hh;
            *(uint32_t*)(HD1 + (size_t)r0 * S256B + cw * 2) = ll;
            splitf(fmaxf(c[2] + sb[cw], 0.f), fmaxf(c[3] + sb[cw + 1], 0.f), hh, ll);
            *(uint32_t*)(HD0 + (size_t)(r0 + 8) * S256B + cw * 2) = hh;
            *(uint32_t*)(HD1 + (size_t)(r0 + 8) * S256B + cw * 2) = ll;
        }
}

// ---------------------------------------------------------------------------
// Head P2: out tile = H @ W2 + b2. grid = 64 tiles.
// ---------------------------------------------------------------------------
__global__ __launch_bounds__(NTHR)
void head_p2(const float* __restrict__ b2, float* __restrict__ out) {
    extern __shared__ uint8_t raw[];
    const uint32_t base = sptr(raw);
    __shared__ float sb2[CDIM];
    int tid = threadIdx.x, wid = tid >> 5, lane = tid & 31;
    int t = blockIdx.x;
    int row0 = t * TILE;

    cpa_copy(base + HP2_HH, g_Himg[0] + t * HIMG, HIMG, tid);
    cpa_copy(base + HP2_HL, g_Himg[1] + t * HIMG, HIMG, tid);
    cpa_copy(base + HP2_WH, g_W2T[0], 8448, tid);
    cpa_copy(base + HP2_WL, g_W2T[1], 8448, tid);
    cpa_commit();
    if (tid < CDIM) sb2[tid] = b2[tid];
    cpa_wait0();
    __syncthreads();

    if (wid < 4) {
        const int mh = wid >> 1, nq = wid & 1;
        const int g = lane >> 2, cp = (lane & 3) * 2;
        float acc[2 * 1 * 4];
#pragma unroll
        for (int i = 0; i < 8; i++) acc[i] = 0.f;
        wgemm<1, 16, S256B, S256B>(acc, base + HP2_HH, base + HP2_HL,
                                   base + HP2_WH, base + HP2_WL, mh * 32, nq * 8, lane);
#pragma unroll
        for (int ms = 0; ms < 2; ms++) {
            int r = row0 + mh * 32 + ms * 16 + g;
            int c0 = nq * 8 + cp;
            float* c = acc + ms * 4;
            out[r * CDIM + c0]           = c[0] + sb2[c0];
            out[r * CDIM + c0 + 1]       = c[1] + sb2[c0 + 1];
            out[(r + 8) * CDIM + c0]     = c[2] + sb2[c0];
            out[(r + 8) * CDIM + c0 + 1] = c[3] + sb2[c0 + 1];
        }
    }
}

// ---------------------------------------------------------------------------
extern "C" void kernel_launch(void* const* d_in, const int* in_sizes, int n_in,
                              void* d_out, int out_size) {
    const int*   entity_ids = (const int*)d_in[0];
    const int*   module_ids = (const int*)d_in[1];
    const float* emb        = (const float*)d_in[2];
    const float* W_in       = (const float*)d_in[3];
    const float* b_in       = (const float*)d_in[4];
    const float* W_bias     = (const float*)d_in[5];
    const float* b_bias     = (const float*)d_in[6];
    const float* W_f        = (const float*)d_in[7];
    const float* b_f        = (const float*)d_in[8];
    const float* W1         = (const float*)d_in[9];
    const float* b1         = (const float*)d_in[10];
    const float* W2         = (const float*)d_in[11];
    const float* b2         = (const float*)d_in[12];
    float* out = (float*)d_out;

    cudaFuncSetAttribute(step_p1, cudaFuncAttributeMaxDynamicSharedMemorySize, P1_SMEM);
    cudaFuncSetAttribute(step_p2, cudaFuncAttributeMaxDynamicSharedMemorySize, P2_SMEM);
    cudaFuncSetAttribute(head_p1, cudaFuncAttributeMaxDynamicSharedMemorySize, P1_SMEM);
    cudaFuncSetAttribute(head_p2, cudaFuncAttributeMaxDynamicSharedMemorySize, HP2_SMEM);

    setup_kernel<<<NSTEPS, NTHR>>>(module_ids);
    xform_kernel<<<dim3(32, 26), NTHR>>>(W_in, W_bias, W_f, W1, W2);
    for (int s = 0; s < NSTEPS; s++) {
        step_p1<<<2 * MAXT, NTHR, P1_SMEM>>>(s, emb, entity_ids, b_in, b_bias);
        step_p2<<<2 * MAXT, NTHR, P2_SMEM>>>(s, b_f);
    }
    head_p1<<<2 * (BB / TILE), NTHR, P1_SMEM>>>(b1);
    head_p2<<<BB / TILE, NTHR, HP2_SMEM>>>(b2, out);
}